// round 14
// baseline (speedup 1.0000x reference)
#include <cuda_runtime.h>
#include <cuda_bf16.h>
#include <math.h>

// ---------------- problem constants ----------------
#define STEPS 20000
#define NCOL  2048
#define CH    50            // steps per chunk
#define NCH   (STEPS/CH)    // 400 chunks
#define NWORK (NCH * NCOL)
#define NBINS 200000
#define HISTN (NBINS + 1)
#define DEPC  5             // k_chunk pipeline depth (1-step stages)
#define DEPM  8             // k_main  pipeline depth (1-step stages)
#define NF1W  4             // f1 words per chunk-column (ceil(50/16))
#define BG    10
#define NBG   (NCH/BG)      // 40
#define THB   1024          // threads per heavy block (2 cols each)

#define R1_SUM_D 123020000.0
__device__ __constant__ float c_invr[4] = {
    1.0f / 1.0e6f, (float)(1.0 / R1_SUM_D), 1.0f / 1.0e5f, (float)(1.0 / 0.2)
};

__device__ __forceinline__ void get_thresholds(float& A, float& B, float& C) {
    const double c0 = 50000000.0 / R1_SUM_D;
    const double c2 = c0 + 3000000.0 / R1_SUM_D;
    const double c3 = c2 + 20000.0 / R1_SUM_D;
    A = (float)c0; B = (float)c2; C = (float)c3;
}

// ---- cp.async helpers ----
__device__ __forceinline__ void cpa8(unsigned smem, const void* g) {
    asm volatile("cp.async.ca.shared.global [%0], [%1], 8;" :: "r"(smem), "l"(g));
}
__device__ __forceinline__ void cpa_commit() {
    asm volatile("cp.async.commit_group;" ::: "memory");
}
template <int N>
__device__ __forceinline__ void cpa_wait() {
    asm volatile("cp.async.wait_group %0;" :: "n"(N) : "memory");
}

// ---- pinned loads ----
__device__ __forceinline__ float4 vldg_f4(const float4* p) {
    float4 v;
    asm volatile("ld.global.nc.v4.f32 {%0,%1,%2,%3}, [%4];"
                 : "=f"(v.x), "=f"(v.y), "=f"(v.z), "=f"(v.w) : "l"(p));
    return v;
}
__device__ __forceinline__ unsigned vldg_u32(const unsigned* p) {
    unsigned v; asm volatile("ld.global.nc.u32 %0, [%1];" : "=r"(v) : "l"(p)); return v;
}

// ---------------- device scratch ----------------
__device__ float4        g_dwl[NWORK];
__device__ unsigned      g_maps[NWORK];
__device__ unsigned char g_entry[NWORK];
__device__ float         g_offs[NWORK];
__device__ unsigned      g_f1[(size_t)NCH * NF1W * NCOL];  // 2-bit f1, 16 steps/word
__device__ int           g_hist[HISTN];

__device__ __forceinline__ int f1_of(float u, float A, float B, float C) {
    return (u < A) ? 0 : ((u < B) ? 2 : ((u < C) ? 3 : 0));
}
__device__ __forceinline__ int advance(int s, int f1) {
    return (s == 0) ? 1 : ((s == 1) ? f1 : 0);
}
__device__ __forceinline__ float invr_of(int s) {
    return (s == 0) ? c_invr[0] : ((s == 1) ? c_invr[1] : ((s == 2) ? c_invr[2] : c_invr[3]));
}

__device__ __forceinline__ int bucket_arith(float t) {
    int j = (int)ceilf(t * 500.0f);
    j = max(0, min(j, NBINS));
    j += (j < NBINS) && ((float)j * 0.002f < t);
    j += (j < NBINS) && ((float)j * 0.002f < t);
    j -= (j > 0) && ((float)(j - 1) * 0.002f >= t);
    j -= (j > 0) && ((float)(j - 1) * 0.002f >= t);
    return j;
}

// ---------------- K0: zero histogram ----------------
__global__ void k_zero() {
    int i = blockIdx.x * blockDim.x + threadIdx.x;
    if (i < HISTN) g_hist[i] = 0;
}

// ---------------- K1: block = chunk over ALL columns (contiguous rows) ----------------
// smem layout per stage: [uc 2048 floats | ue 2048 floats]
extern __shared__ float sh_dyn[];
__global__ void __launch_bounds__(THB) k_chunk(const float* __restrict__ ucat,
                                               const float* __restrict__ uexp) {
    int tid  = threadIdx.x;
    int c    = blockIdx.x;            // chunk
    int col0 = 2 * tid;
    float A, B, C; get_thresholds(A, B, C);

    const float* pc = ucat + (size_t)c * CH * NCOL + col0;
    const float* pe = uexp + (size_t)c * CH * NCOL + col0;

    unsigned sb = (unsigned)__cvta_generic_to_shared(sh_dyn) + col0 * 4;
    const unsigned STG_B = 4096 * 4;          // bytes per stage
    const unsigned UE_B  = 2048 * 4;

    #pragma unroll
    for (int s = 0; s < DEPC; s++) {
        cpa8(sb + s * STG_B,        pc + (size_t)s * NCOL);
        cpa8(sb + s * STG_B + UE_B, pe + (size_t)s * NCOL);
        cpa_commit();
    }

    int   sA[2], sB[2], sC[2];
    float aA[2], aB[2], aT[2], g0[2];
    unsigned fw[2] = {0u, 0u};
    #pragma unroll
    for (int q = 0; q < 2; q++) {
        sA[q] = 0; sB[q] = 1; sC[q] = 0;
        aA[q] = 0.f; aB[q] = 0.f; aT[q] = 0.f; g0[q] = 0.f;
    }

    for (int k = 0; k < CH; k++) {
        if (k < CH - DEPC)       cpa_wait<DEPC - 1>();
        else if (k == CH - DEPC) cpa_wait<0>();
        int buf = k % DEPC;

        float2 uc2 = *(float2*)&sh_dyn[buf * 4096 + col0];
        float2 ue2 = *(float2*)&sh_dyn[buf * 4096 + 2048 + col0];
        float u1a[2] = {uc2.x, uc2.y};
        float u2a[2] = {ue2.x, ue2.y};

        #pragma unroll
        for (int q = 0; q < 2; q++) {
            float gg = -__logf(1.0f - u2a[q]);
            int   f  = f1_of(u1a[q], A, B, C);
            fw[q] |= (unsigned)f << (2 * (k & 15));
            if (k == 0) {
                g0[q] = gg;
                aA[q] = gg * c_invr[0];
                aB[q] = gg * c_invr[1];
                sA[q] = 1; sB[q] = f; sC[q] = 0;
            } else {
                aT[q] = fmaf(gg, invr_of(sC[q]), aT[q]);
                aA[q] = fmaf(gg, invr_of(sA[q]), aA[q]);
                aB[q] = fmaf(gg, invr_of(sB[q]), aB[q]);
                sC[q] = advance(sC[q], f);
                sA[q] = advance(sA[q], f);
                sB[q] = advance(sB[q], f);
            }
        }
        if ((k & 15) == 15 || k == CH - 1) {
            int w = k >> 4;
            uint2 w2; w2.x = fw[0]; w2.y = fw[1];
            *(uint2*)&g_f1[((size_t)c * NF1W + w) * NCOL + col0] = w2;
            fw[0] = 0u; fw[1] = 0u;
        }

        if (k + DEPC < CH) {
            int nb = (k + DEPC) % DEPC;
            cpa8(sb + nb * STG_B,        pc + (size_t)(k + DEPC) * NCOL);
            cpa8(sb + nb * STG_B + UE_B, pe + (size_t)(k + DEPC) * NCOL);
            cpa_commit();
        }
    }

    #pragma unroll
    for (int q = 0; q < 2; q++) {
        int gidx = c * NCOL + col0 + q;
        float4 d;
        d.x = aA[q];
        d.y = aB[q];
        d.z = fmaf(g0[q], c_invr[2], aT[q]);
        d.w = fmaf(g0[q], c_invr[3], aT[q]);
        g_dwl[gidx]  = d;
        g_maps[gidx] = (unsigned)sA[q] | ((unsigned)sB[q] << 8) | ((unsigned)sC[q] << 16);
    }
}

// ---------------- K2: per-column scan over chunks ----------------
__global__ void __launch_bounds__(256) k_boundary() {
    int col = blockIdx.x * blockDim.x + threadIdx.x;   // 0..2047
    int s = 0;
    double t = 0.0;

    float4   bdA[BG], bdB[BG];
    unsigned bmA[BG], bmB[BG];
    #pragma unroll
    for (int jj = 0; jj < BG; jj++) {
        bdA[jj] = vldg_f4(&g_dwl[jj * NCOL + col]);
        bmA[jj] = vldg_u32(&g_maps[jj * NCOL + col]);
    }

    for (int g = 0; g < NBG; g += 2) {
        if (g + 1 < NBG) {
            #pragma unroll
            for (int jj = 0; jj < BG; jj++) {
                bdB[jj] = vldg_f4(&g_dwl[((g + 1) * BG + jj) * NCOL + col]);
                bmB[jj] = vldg_u32(&g_maps[((g + 1) * BG + jj) * NCOL + col]);
            }
        }
        #pragma unroll
        for (int jj = 0; jj < BG; jj++) {
            int idx = (g * BG + jj) * NCOL + col;
            g_entry[idx] = (unsigned char)s;
            g_offs[idx]  = (float)t;
            float4 d = bdA[jj];
            float dv = (s == 0) ? d.x : (s == 1) ? d.y : (s == 2) ? d.z : d.w;
            t += (double)dv;
            unsigned m = bmA[jj];
            int sh = (s < 2) ? s : 2;
            s = (int)((m >> (8 * sh)) & 3u);
        }
        if (g + 2 < NBG) {
            #pragma unroll
            for (int jj = 0; jj < BG; jj++) {
                bdA[jj] = vldg_f4(&g_dwl[((g + 2) * BG + jj) * NCOL + col]);
                bmA[jj] = vldg_u32(&g_maps[((g + 2) * BG + jj) * NCOL + col]);
            }
        }
        #pragma unroll
        for (int jj = 0; jj < BG; jj++) {
            int idx = ((g + 1) * BG + jj) * NCOL + col;
            g_entry[idx] = (unsigned char)s;
            g_offs[idx]  = (float)t;
            float4 d = bdB[jj];
            float dv = (s == 0) ? d.x : (s == 1) ? d.y : (s == 2) ? d.z : d.w;
            t += (double)dv;
            unsigned m = bmB[jj];
            int sh = (s < 2) ? s : 2;
            s = (int)((m >> (8 * sh)) & 3u);
        }
    }
}

// ---------------- K3: final resolve; block = chunk over ALL columns ----------------
__global__ void __launch_bounds__(THB) k_main(const float* __restrict__ uexp,
                                              float* __restrict__ phot,
                                              float* __restrict__ cum) {
    int tid  = threadIdx.x;
    int c    = blockIdx.x;
    int col0 = 2 * tid;

    const float* pe = uexp + (size_t)c * CH * NCOL + col0;
    float* pp = phot + (size_t)c * CH * NCOL + col0;
    float* pt = cum  + (size_t)c * CH * NCOL + col0;

    unsigned sb = (unsigned)__cvta_generic_to_shared(sh_dyn) + col0 * 4;
    const unsigned STG_B = 2048 * 4;

    #pragma unroll
    for (int s = 0; s < DEPM; s++) {
        cpa8(sb + s * STG_B, pe + (size_t)s * NCOL);
        cpa_commit();
    }

    // f1 words (4 per column) + entry + offset
    unsigned fwords[2][NF1W];
    #pragma unroll
    for (int w = 0; w < NF1W; w++) {
        fwords[0][w] = vldg_u32(&g_f1[((size_t)c * NF1W + w) * NCOL + col0]);
        fwords[1][w] = vldg_u32(&g_f1[((size_t)c * NF1W + w) * NCOL + col0 + 1]);
    }
    int idx0 = c * NCOL + col0;
    uchar2 e2 = *(const uchar2*)&g_entry[idx0];
    float2 o2 = *(const float2*)&g_offs[idx0];

    int   s[2]  = {e2.x, e2.y};
    float t[2]  = {o2.x, o2.y};
    int   jb[2]; float edge[2]; int rc[2];
    #pragma unroll
    for (int q = 0; q < 2; q++) {
        jb[q] = bucket_arith(t[q]);
        edge[q] = (float)jb[q] * 0.002f;
        rc[q] = 0;
    }
    int nz = 0;

    const float IR0 = c_invr[0], IR1 = c_invr[1], IR2 = c_invr[2], IR3 = c_invr[3];

    for (int k = 0; k < CH; k++) {
        if (k < CH - DEPM)       cpa_wait<DEPM - 1>();
        else if (k == CH - DEPM) cpa_wait<0>();
        int buf = k % DEPM;

        float2 ue2 = *(float2*)&sh_dyn[buf * 2048 + col0];
        float ua[2] = {ue2.x, ue2.y};
        float pv[2], tv[2];
        int w = k >> 4, bi = 2 * (k & 15);

        #pragma unroll
        for (int q = 0; q < 2; q++) {
            int   st = s[q];
            float gg = -__logf(1.0f - ua[q]);
            float ir = (st == 0) ? IR0 : ((st == 1) ? IR1 : ((st == 2) ? IR2 : IR3));
            t[q] += gg * ir;
            bool ph = (st == 0);
            pv[q] = ph ? 1.0f : 0.0f;
            tv[q] = t[q];
            if (ph) {
                if (t[q] > edge[q]) {
                    if (rc[q]) atomicAdd(&g_hist[jb[q]], rc[q]);
                    jb[q] = bucket_arith(t[q]);
                    edge[q] = (float)jb[q] * 0.002f; rc[q] = 1;
                } else rc[q]++;
            } else nz++;
            int f = (int)((fwords[q][w] >> bi) & 3u);
            s[q] = advance(st, f);
        }
        float2 wp; wp.x = pv[0]; wp.y = pv[1];
        float2 wt; wt.x = tv[0]; wt.y = tv[1];
        __stcs((float2*)(pp + (size_t)k * NCOL), wp);
        __stcs((float2*)(pt + (size_t)k * NCOL), wt);

        if (k + DEPM < CH) {
            int nb = (k + DEPM) % DEPM;
            cpa8(sb + nb * STG_B, pe + (size_t)(k + DEPM) * NCOL);
            cpa_commit();
        }
    }
    #pragma unroll
    for (int q = 0; q < 2; q++)
        if (rc[q]) atomicAdd(&g_hist[jb[q]], rc[q]);

    int tot = __reduce_add_sync(0xffffffffu, nz);
    if ((threadIdx.x & 31) == 0 && tot) atomicAdd(&g_hist[0], tot);
}

// ---------------- K4: int hist -> float32 output tail ----------------
__global__ void k_hist_out(float* __restrict__ out_hist) {
    int i = blockIdx.x * blockDim.x + threadIdx.x;
    if (i < HISTN) out_hist[i] = (float)g_hist[i];
}

// ---------------- launch ----------------
extern "C" void kernel_launch(void* const* d_in, const int* in_sizes, int n_in,
                              void* d_out, int out_size) {
    const float* ucat = (const float*)d_in[0];
    const float* uexp = (const float*)d_in[1];
    float* out = (float*)d_out;

    const size_t n_elem = (size_t)STEPS * NCOL;
    float* out_phot = out;
    float* out_cum  = out + n_elem;
    float* out_hist = out + 2 * n_elem;

    const int smem_chunk = DEPC * 4096 * 4;   // 80 KB
    const int smem_main  = DEPM * 2048 * 4;   // 64 KB
    cudaFuncSetAttribute(k_chunk, cudaFuncAttributeMaxDynamicSharedMemorySize, smem_chunk);
    cudaFuncSetAttribute(k_main,  cudaFuncAttributeMaxDynamicSharedMemorySize, smem_main);

    const int th = 256;
    const int hist_blocks = (HISTN + th - 1) / th;

    k_zero<<<hist_blocks, th>>>();
    k_chunk<<<NCH, THB, smem_chunk>>>(ucat, uexp);
    k_boundary<<<NCOL / th, th>>>();
    k_main<<<NCH, THB, smem_main>>>(uexp, out_phot, out_cum);
    k_hist_out<<<hist_blocks, th>>>(out_hist);
}

// round 15
// speedup vs baseline: 1.4175x; 1.4175x over previous
#include <cuda_runtime.h>
#include <cuda_bf16.h>
#include <math.h>

// ---------------- problem constants ----------------
#define STEPS 20000
#define NCOL  2048
#define CH    100           // steps per chunk
#define NCH   (STEPS/CH)    // 200 chunks
#define NWORK (NCH * NCOL)
#define NBINS 200000
#define HISTN (NBINS + 1)
#define NST   (CH/4)        // 25 four-step stages per chunk
#define DEPC  4             // k_chunk cp.async pipeline depth
#define DEPM  6             // k_main  cp.async pipeline depth
#define CPB   (NCOL/256)    // 8 col-groups per chunk
#define NF1W  7             // ceil(CH/16) f1 words per chunk-column
#define BG    10            // boundary prefetch group (chunks)
#define NBG   (NCH/BG)      // 20

#define R1_SUM_D 123020000.0
__device__ __constant__ float c_invr[4] = {
    1.0f / 1.0e6f, (float)(1.0 / R1_SUM_D), 1.0f / 1.0e5f, (float)(1.0 / 0.2)
};

__device__ __forceinline__ void get_thresholds(float& A, float& B, float& C) {
    const double c0 = 50000000.0 / R1_SUM_D;
    const double c2 = c0 + 3000000.0 / R1_SUM_D;
    const double c3 = c2 + 20000.0 / R1_SUM_D;
    A = (float)c0; B = (float)c2; C = (float)c3;
}

// ---- cp.async helpers ----
__device__ __forceinline__ void cpa4(unsigned smem, const void* g) {
    asm volatile("cp.async.ca.shared.global [%0], [%1], 4;" :: "r"(smem), "l"(g));
}
__device__ __forceinline__ void cpa_commit() {
    asm volatile("cp.async.commit_group;" ::: "memory");
}
template <int N>
__device__ __forceinline__ void cpa_wait() {
    asm volatile("cp.async.wait_group %0;" :: "n"(N) : "memory");
}

// ---- pinned loads (boundary scan + f1 fetch) ----
__device__ __forceinline__ float4 vldg_f4(const float4* p) {
    float4 v;
    asm volatile("ld.global.nc.v4.f32 {%0,%1,%2,%3}, [%4];"
                 : "=f"(v.x), "=f"(v.y), "=f"(v.z), "=f"(v.w) : "l"(p));
    return v;
}
__device__ __forceinline__ unsigned vldg_u32(const unsigned* p) {
    unsigned v; asm volatile("ld.global.nc.u32 %0, [%1];" : "=r"(v) : "l"(p)); return v;
}

// ---------------- device scratch ----------------
__device__ float4        g_dwl[NWORK];                 // {dA,dB,dC,dD}
__device__ unsigned      g_maps[NWORK];
__device__ unsigned char g_entry[NWORK];
__device__ float         g_offs[NWORK];
__device__ unsigned      g_f1[(size_t)NCH * NF1W * NCOL]; // 2-bit f1, 16 steps/word
__device__ int           g_hist[HISTN];

__device__ __forceinline__ int f1_of(float u, float A, float B, float C) {
    return (u < A) ? 0 : ((u < B) ? 2 : ((u < C) ? 3 : 0));
}
__device__ __forceinline__ int advance(int s, int f1) {
    return (s == 0) ? 1 : ((s == 1) ? f1 : 0);
}
__device__ __forceinline__ float invr_of(int s) {
    return (s == 0) ? c_invr[0] : ((s == 1) ? c_invr[1] : ((s == 2) ? c_invr[2] : c_invr[3]));
}

// smallest j in [0,NBINS] with (float)j*0.002f >= t (branchless +-2 correction)
__device__ __forceinline__ int bucket_arith(float t) {
    int j = (int)ceilf(t * 500.0f);
    j = max(0, min(j, NBINS));
    j += (j < NBINS) && ((float)j * 0.002f < t);
    j += (j < NBINS) && ((float)j * 0.002f < t);
    j -= (j > 0) && ((float)(j - 1) * 0.002f >= t);
    j -= (j > 0) && ((float)(j - 1) * 0.002f >= t);
    return j;
}

// ---------------- K0: zero histogram ----------------
__global__ void k_zero() {
    int i = blockIdx.x * blockDim.x + threadIdx.x;
    if (i < HISTN) g_hist[i] = 0;
}

// ---------------- K1: chunk maps + dwell totals + f1 stream (cp.async) ----------------
__global__ void __launch_bounds__(256) k_chunk(const float* __restrict__ ucat,
                                               const float* __restrict__ uexp) {
    __shared__ float s_uc[DEPC][4][256];
    __shared__ float s_ue[DEPC][4][256];

    int tid = threadIdx.x;
    int c   = blockIdx.x >> 3;          // chunk
    int cg  = blockIdx.x & 7;           // col group
    int col = cg * 256 + tid;
    float A, B, C; get_thresholds(A, B, C);

    const float* pc = ucat + (size_t)c * CH * NCOL + col;
    const float* pe = uexp + (size_t)c * CH * NCOL + col;

    unsigned uc_s = (unsigned)__cvta_generic_to_shared(&s_uc[0][0][tid]);
    unsigned ue_s = (unsigned)__cvta_generic_to_shared(&s_ue[0][0][tid]);
    const unsigned STG_B = 4 * 256 * 4;
    const unsigned ROW_B = 256 * 4;

    #pragma unroll
    for (int s = 0; s < DEPC; s++) {
        #pragma unroll
        for (int j = 0; j < 4; j++) {
            cpa4(uc_s + s * STG_B + j * ROW_B, pc + (size_t)(4 * s + j) * NCOL);
            cpa4(ue_s + s * STG_B + j * ROW_B, pe + (size_t)(4 * s + j) * NCOL);
        }
        cpa_commit();
    }

    int   sA = 0, sB = 1, sC = 0;
    float aA = 0.f, aB = 0.f, aT = 0.f, g0 = 0.f;
    unsigned fw = 0u;

    for (int s = 0; s < NST; s++) {
        if (s < NST - DEPC)       cpa_wait<DEPC - 1>();
        else if (s == NST - DEPC) cpa_wait<0>();
        int buf = s % DEPC;

        #pragma unroll
        for (int j = 0; j < 4; j++) {
            const int k = 4 * s + j;
            float u1 = s_uc[buf][j][tid];
            float u2 = s_ue[buf][j][tid];
            float gg = -__logf(1.0f - u2);
            int   f  = f1_of(u1, A, B, C);
            fw |= (unsigned)f << (2 * (k & 15));
            if (k == 0) {
                g0 = gg;
                aA = gg * c_invr[0];
                aB = gg * c_invr[1];
                sA = 1; sB = f; sC = 0;
            } else {
                aT = fmaf(gg, invr_of(sC), aT);
                aA = fmaf(gg, invr_of(sA), aA);
                aB = fmaf(gg, invr_of(sB), aB);
                sC = advance(sC, f);
                sA = advance(sA, f);
                sB = advance(sB, f);
            }
            if ((k & 15) == 15 || k == CH - 1) {
                g_f1[((size_t)c * NF1W + (k >> 4)) * NCOL + col] = fw;
                fw = 0u;
            }
        }

        if (s + DEPC < NST) {
            int nb = (s + DEPC) % DEPC;
            #pragma unroll
            for (int j = 0; j < 4; j++) {
                cpa4(uc_s + nb * STG_B + j * ROW_B, pc + (size_t)(4 * (s + DEPC) + j) * NCOL);
                cpa4(ue_s + nb * STG_B + j * ROW_B, pe + (size_t)(4 * (s + DEPC) + j) * NCOL);
            }
            cpa_commit();
        }
    }

    int gidx = c * NCOL + col;
    float4 d;
    d.x = aA;
    d.y = aB;
    d.z = fmaf(g0, c_invr[2], aT);
    d.w = fmaf(g0, c_invr[3], aT);
    g_dwl[gidx]  = d;
    g_maps[gidx] = (unsigned)sA | ((unsigned)sB << 8) | ((unsigned)sC << 16);
}

// ---------------- K2: per-column scan over chunks ----------------
__global__ void __launch_bounds__(256) k_boundary() {
    int col = blockIdx.x * blockDim.x + threadIdx.x;   // 0..2047
    int s = 0;
    double t = 0.0;

    float4   bdA[BG], bdB[BG];
    unsigned bmA[BG], bmB[BG];
    #pragma unroll
    for (int jj = 0; jj < BG; jj++) {
        bdA[jj] = vldg_f4(&g_dwl[jj * NCOL + col]);
        bmA[jj] = vldg_u32(&g_maps[jj * NCOL + col]);
    }

    for (int g = 0; g < NBG; g += 2) {
        if (g + 1 < NBG) {
            #pragma unroll
            for (int jj = 0; jj < BG; jj++) {
                bdB[jj] = vldg_f4(&g_dwl[((g + 1) * BG + jj) * NCOL + col]);
                bmB[jj] = vldg_u32(&g_maps[((g + 1) * BG + jj) * NCOL + col]);
            }
        }
        #pragma unroll
        for (int jj = 0; jj < BG; jj++) {
            int idx = (g * BG + jj) * NCOL + col;
            g_entry[idx] = (unsigned char)s;
            g_offs[idx]  = (float)t;
            float4 d = bdA[jj];
            float dv = (s == 0) ? d.x : (s == 1) ? d.y : (s == 2) ? d.z : d.w;
            t += (double)dv;
            unsigned m = bmA[jj];
            int sh = (s < 2) ? s : 2;
            s = (int)((m >> (8 * sh)) & 3u);
        }
        if (g + 2 < NBG) {
            #pragma unroll
            for (int jj = 0; jj < BG; jj++) {
                bdA[jj] = vldg_f4(&g_dwl[((g + 2) * BG + jj) * NCOL + col]);
                bmA[jj] = vldg_u32(&g_maps[((g + 2) * BG + jj) * NCOL + col]);
            }
        }
        #pragma unroll
        for (int jj = 0; jj < BG; jj++) {
            int idx = ((g + 1) * BG + jj) * NCOL + col;
            g_entry[idx] = (unsigned char)s;
            g_offs[idx]  = (float)t;
            float4 d = bdB[jj];
            float dv = (s == 0) ? d.x : (s == 1) ? d.y : (s == 2) ? d.z : d.w;
            t += (double)dv;
            unsigned m = bmB[jj];
            int sh = (s < 2) ? s : 2;
            s = (int)((m >> (8 * sh)) & 3u);
        }
    }
}

// ---------------- K3: final resolve (cp.async uexp; states via f1 recurrence) ----------------
__global__ void __launch_bounds__(256) k_main(const float* __restrict__ uexp,
                                              float* __restrict__ phot,
                                              float* __restrict__ cum) {
    __shared__ float s_ue[DEPM][4][256];

    int tid = threadIdx.x;
    int c   = blockIdx.x >> 3;
    int cg  = blockIdx.x & 7;
    int col = cg * 256 + tid;

    const float* pe = uexp + (size_t)c * CH * NCOL + col;
    float* pp = phot + (size_t)c * CH * NCOL + col;
    float* pt = cum  + (size_t)c * CH * NCOL + col;

    unsigned ue_s = (unsigned)__cvta_generic_to_shared(&s_ue[0][0][tid]);
    const unsigned STG_B = 4 * 256 * 4;
    const unsigned ROW_B = 256 * 4;

    #pragma unroll
    for (int s = 0; s < DEPM; s++) {
        #pragma unroll
        for (int j = 0; j < 4; j++)
            cpa4(ue_s + s * STG_B + j * ROW_B, pe + (size_t)(4 * s + j) * NCOL);
        cpa_commit();
    }

    // f1 words + entry + offset (issued while pipeline fills)
    unsigned fwords[NF1W];
    #pragma unroll
    for (int w = 0; w < NF1W; w++)
        fwords[w] = vldg_u32(&g_f1[((size_t)c * NF1W + w) * NCOL + col]);

    int gidx = c * NCOL + col;
    int   st = (int)g_entry[gidx];   // exact: advance() maps 2/3 -> 0 uniformly
    float t  = g_offs[gidx];

    int   jb = bucket_arith(t);
    float edge = (float)jb * 0.002f;
    int   rc = 0, nz = 0;

    const float IR0 = c_invr[0], IR1 = c_invr[1], IR2 = c_invr[2], IR3 = c_invr[3];

    for (int s = 0; s < NST; s++) {
        if (s < NST - DEPM)       cpa_wait<DEPM - 1>();
        else if (s == NST - DEPM) cpa_wait<0>();
        int buf = s % DEPM;

        #pragma unroll
        for (int j = 0; j < 4; j++) {
            const int k = 4 * s + j;
            float u2 = s_ue[buf][j][tid];
            float gg = -__logf(1.0f - u2);
            float ir = (st == 0) ? IR0 : ((st == 1) ? IR1 : ((st == 2) ? IR2 : IR3));
            t += gg * ir;
            bool ph = (st == 0);
            __stcs(pp + (size_t)k * NCOL, ph ? 1.0f : 0.0f);
            __stcs(pt + (size_t)k * NCOL, t);
            if (ph) {
                if (t > edge) {
                    if (rc) atomicAdd(&g_hist[jb], rc);
                    jb = bucket_arith(t); edge = (float)jb * 0.002f; rc = 1;
                } else rc++;
            } else nz++;
            int f = (int)((fwords[k >> 4] >> (2 * (k & 15))) & 3u);
            st = advance(st, f);
        }

        if (s + DEPM < NST) {
            int nb = (s + DEPM) % DEPM;
            #pragma unroll
            for (int j = 0; j < 4; j++)
                cpa4(ue_s + nb * STG_B + j * ROW_B, pe + (size_t)(4 * (s + DEPM) + j) * NCOL);
            cpa_commit();
        }
    }
    if (rc) atomicAdd(&g_hist[jb], rc);

    int tot = __reduce_add_sync(0xffffffffu, nz);
    if ((threadIdx.x & 31) == 0 && tot) atomicAdd(&g_hist[0], tot);
}

// ---------------- K4: int hist -> float32 output tail ----------------
__global__ void k_hist_out(float* __restrict__ out_hist) {
    int i = blockIdx.x * blockDim.x + threadIdx.x;
    if (i < HISTN) out_hist[i] = (float)g_hist[i];
}

// ---------------- launch ----------------
extern "C" void kernel_launch(void* const* d_in, const int* in_sizes, int n_in,
                              void* d_out, int out_size) {
    const float* ucat = (const float*)d_in[0];
    const float* uexp = (const float*)d_in[1];
    float* out = (float*)d_out;

    const size_t n_elem = (size_t)STEPS * NCOL;
    float* out_phot = out;
    float* out_cum  = out + n_elem;
    float* out_hist = out + 2 * n_elem;

    const int th = 256;
    const int hist_blocks = (HISTN + th - 1) / th;
    const int work_blocks = NCH * CPB;            // 1600

    k_zero<<<hist_blocks, th>>>();
    k_chunk<<<work_blocks, th>>>(ucat, uexp);
    k_boundary<<<NCOL / th, th>>>();
    k_main<<<work_blocks, th>>>(uexp, out_phot, out_cum);
    k_hist_out<<<hist_blocks, th>>>(out_hist);
}